// round 14
// baseline (speedup 1.0000x reference)
#include <cuda_runtime.h>
#include <cuda_fp16.h>
#include <stdint.h>

#define NB   4096
#define NOUTC 3

// ---- shared memory (bytes): ROOT(4x128 f32) | B0: 256 rows | B1: 128 rows ----
// Row = 256 fp16 (512B) as 4 sw128 chunks x [rows x 128B].
#define OFF_ROOT 0
#define OFF_B0   2048
#define B0_CS    32768
#define OFF_B1   (OFF_B0 + 4 * B0_CS)       // 133120
#define B1_CS    16384
#define SMEM_BYTES (OFF_B1 + 4 * B1_CS)     // 198656 (1 CTA/SM)

__device__ int g_tok_is_i32;

__global__ void detect_tok_kernel(const unsigned int* __restrict__ w) {
    __shared__ int s;
    if (threadIdx.x == 0) s = 0;
    __syncthreads();
    int any = 0;
    for (int i = threadIdx.x; i < 2048; i += 256)
        any |= (w[2 * i + 1] != 0u);
    if (any) atomicOr(&s, 1);
    __syncthreads();
    if (threadIdx.x == 0) g_tok_is_i32 = s;
}

static __device__ __forceinline__ uint32_t sw128(uint32_t b) {
    return b ^ ((b >> 3) & 0x70);
}
static __device__ __forceinline__ uint32_t smem_u32(const void* p) {
    uint32_t a;
    asm("{ .reg .u64 t; cvta.to.shared.u64 t, %1; cvt.u32.u64 %0, t; }" : "=r"(a) : "l"(p));
    return a;
}
static __device__ __forceinline__ void ldsm4(uint32_t addr, uint32_t& r0, uint32_t& r1,
                                             uint32_t& r2, uint32_t& r3) {
    asm volatile("ldmatrix.sync.aligned.m8n8.x4.shared.b16 {%0,%1,%2,%3}, [%4];"
                 : "=r"(r0), "=r"(r1), "=r"(r2), "=r"(r3) : "r"(addr));
}
static __device__ __forceinline__ void mma_f16(float& d0, float& d1, float& d2, float& d3,
                                               const uint32_t a[4], uint32_t b0, uint32_t b1) {
    asm volatile("mma.sync.aligned.m16n8k16.row.col.f32.f16.f16.f32 "
                 "{%0,%1,%2,%3}, {%4,%5,%6,%7}, {%8,%9}, {%0,%1,%2,%3};"
                 : "+f"(d0), "+f"(d1), "+f"(d2), "+f"(d3)
                 : "r"(a[0]), "r"(a[1]), "r"(a[2]), "r"(a[3]), "r"(b0), "r"(b1));
}
static __device__ __forceinline__ float tanh_fast(float x) {
    float t = __expf(2.0f * x);
    return 1.0f - __fdividef(2.0f, t + 1.0f);
}
static __device__ __forceinline__ uint32_t pack_h2(float x, float y) {
    __half h0 = __float2half_rn(x), h1 = __float2half_rn(y);
    return ((uint32_t)*(uint16_t*)&h1 << 16) | *(uint16_t*)&h0;
}
static __device__ __forceinline__ void store16(char* sm, uint32_t dstHi, uint32_t dcs,
                                               int r, int k, float x) {
    __half h = __float2half_rn(x);
    int chunk = k >> 6;
    uint32_t off = sw128((uint32_t)(r * 128 + (k & 63) * 2));
    *(__half*)(sm + dstHi + (uint32_t)chunk * dcs + off) = h;
}

// One level over 4 trees. Warp = (g2 = n-group, mq = 32-row m-slice).
// Group g2 handles tiles [g2*NT_G, g2*NT_G+ntiles); NTILES_TOT==1 -> group 0 only.
template<int NTILES_TOT, int SPT, bool LAST>
static __device__ __forceinline__ void run_level(
    char* sm, uint32_t sb, uint32_t srcHi, uint32_t scs, uint32_t dstHi, uint32_t dcs,
    const uint32_t A0[16][4], const uint32_t A1[16][4],
    const float bias[4], int mq, int g2, int lane, float* rootp)
{
    const int g = lane >> 3, lr = lane & 7;
    constexpr int NT_G = (NTILES_TOT >= 2) ? NTILES_TOT / 2 : 1;
    const int ntiles = (NTILES_TOT >= 2) ? NT_G : (g2 == 0 ? 1 : 0);
    const int nbase  = (NTILES_TOT >= 2) ? g2 * NT_G : 0;
    uint32_t B[16][2];

    if (ntiles > 0) {                         // prologue: first tile of this group
        const int row = nbase * 8 + lr;
#pragma unroll
        for (int j = 0; j < 8; j++) {
            int kb = j * 64 + g * 16;
            uint32_t off = (uint32_t)((kb >> 7) * scs)
                         + sw128((uint32_t)(row * 128 + (kb & 127)));
            ldsm4(sb + srcHi + off, B[2 * j][0], B[2 * j][1], B[2 * j + 1][0], B[2 * j + 1][1]);
        }
    }

#pragma unroll 1
    for (int nb = 0; nb < ntiles; nb++) {
        // 4 independent chains: (A0,A1) x (even,odd kt)
        float c0[4] = {0.f, 0.f, 0.f, 0.f}, c1[4] = {0.f, 0.f, 0.f, 0.f};
        float c2[4] = {0.f, 0.f, 0.f, 0.f}, c3[4] = {0.f, 0.f, 0.f, 0.f};
#pragma unroll
        for (int kt = 0; kt < 16; kt += 2) {
            mma_f16(c0[0], c0[1], c0[2], c0[3], A0[kt],     B[kt][0],     B[kt][1]);
            mma_f16(c1[0], c1[1], c1[2], c1[3], A0[kt + 1], B[kt + 1][0], B[kt + 1][1]);
            mma_f16(c2[0], c2[1], c2[2], c2[3], A1[kt],     B[kt][0],     B[kt][1]);
            mma_f16(c3[0], c3[1], c3[2], c3[3], A1[kt + 1], B[kt + 1][0], B[kt + 1][1]);
        }

        // prefetch next tile (WAR-safe in issue order), overlapped by epilogue
        if (nb + 1 < ntiles) {
            const int row = (nbase + nb + 1) * 8 + lr;
#pragma unroll
            for (int j = 0; j < 8; j++) {
                int kb = j * 64 + g * 16;
                uint32_t off = (uint32_t)((kb >> 7) * scs)
                             + sw128((uint32_t)(row * 128 + (kb & 127)));
                ldsm4(sb + srcHi + off, B[2 * j][0], B[2 * j][1], B[2 * j + 1][0], B[2 * j + 1][1]);
            }
        }

        float d00 = bias[0] + (c0[0] + c1[0]);   // (e0,    n)
        float d01 = bias[0] + (c0[1] + c1[1]);   // (e0,    n+1)
        float d02 = bias[1] + (c0[2] + c1[2]);   // (e0+8,  n)
        float d03 = bias[1] + (c0[3] + c1[3]);
        float d10 = bias[2] + (c2[0] + c3[0]);   // (e0+16, n)
        float d11 = bias[2] + (c2[1] + c3[1]);
        float d12 = bias[3] + (c2[2] + c3[2]);   // (e0+24, n)
        float d13 = bias[3] + (c2[3] + c3[3]);

        const int e0 = mq * 32 + (lane >> 2);
        const int nL = (nbase + nb) * 8 + 2 * (lane & 3);
        if constexpr (!LAST) {
            if (nL < 4 * SPT) {
                int t0 = nL / SPT, ln0 = nL % SPT;
                int r0 = t0 * (SPT / 2) + (ln0 >> 1), k0 = (ln0 & 1) * 128;
                int n1 = nL + 1, t1 = n1 / SPT, ln1 = n1 % SPT;
                int r1 = t1 * (SPT / 2) + (ln1 >> 1), k1 = (ln1 & 1) * 128;
                store16(sm, dstHi, dcs, r0, k0 + e0,      tanh_fast(d00));
                store16(sm, dstHi, dcs, r1, k1 + e0,      tanh_fast(d01));
                store16(sm, dstHi, dcs, r0, k0 + e0 + 8,  tanh_fast(d02));
                store16(sm, dstHi, dcs, r1, k1 + e0 + 8,  tanh_fast(d03));
                store16(sm, dstHi, dcs, r0, k0 + e0 + 16, tanh_fast(d10));
                store16(sm, dstHi, dcs, r1, k1 + e0 + 16, tanh_fast(d11));
                store16(sm, dstHi, dcs, r0, k0 + e0 + 24, tanh_fast(d12));
                store16(sm, dstHi, dcs, r1, k1 + e0 + 24, tanh_fast(d13));
            }
        } else {
            // SPT==1: n = tree index; lanes with (lane&3)<2 cover trees 0..3
            if ((lane & 3) < 2) {
                int ta = 2 * (lane & 3), tb = ta + 1;
                rootp[ta * 128 + e0]      = tanh_fast(d00);
                rootp[tb * 128 + e0]      = tanh_fast(d01);
                rootp[ta * 128 + e0 + 8]  = tanh_fast(d02);
                rootp[tb * 128 + e0 + 8]  = tanh_fast(d03);
                rootp[ta * 128 + e0 + 16] = tanh_fast(d10);
                rootp[tb * 128 + e0 + 16] = tanh_fast(d11);
                rootp[ta * 128 + e0 + 24] = tanh_fast(d12);
                rootp[tb * 128 + e0 + 24] = tanh_fast(d13);
            }
        }
    }
}

__global__ __launch_bounds__(256, 1)
void tree_kernel(const void* __restrict__ tokens_raw,
                 const float* __restrict__ emb,
                 const float* __restrict__ W_tree,
                 const float* __restrict__ b_tree,
                 const float* __restrict__ W_cls,
                 const float* __restrict__ b_cls,
                 float* __restrict__ out)
{
    extern __shared__ char sm[];
    const uint32_t sb = smem_u32(sm);
    const int tid = threadIdx.x, wq = tid >> 5, lane = tid & 31;
    const int mq = wq & 3, g2 = wq >> 2;
    const int b = blockIdx.x;                 // trees 4b..4b+3

    // ---- leaf gather (512 leaves), shfl-batched MLP-8 ----
    const int is32 = g_tok_is_i32;
    {
        const long long* t64 = (const long long*)tokens_raw;
        const int*       t32 = (const int*)tokens_raw;
#pragma unroll
        for (int p = 0; p < 2; p++) {
            const int myLeaf = p * 256 + wq + 8 * lane;
            int myTok = is32 ? t32[b * 512 + myLeaf]
                             : (int)t64[b * 512 + myLeaf];
#pragma unroll
            for (int grp = 0; grp < 4; grp++) {
                float4 v[8];
#pragma unroll
                for (int j = 0; j < 8; j++) {
                    int i = grp * 8 + j;
                    int tk = __shfl_sync(0xffffffffu, myTok, i);
                    v[j] = ((const float4*)emb)[(long long)tk * 32 + lane];
                }
#pragma unroll
                for (int j = 0; j < 8; j++) {
                    int i = grp * 8 + j;
                    int l = p * 256 + wq + 8 * i;
                    int t = l >> 7, ll = l & 127;
                    int row = t * 64 + (ll >> 1);
                    int kb16 = ((ll & 1) << 7) + lane * 4;
                    int chunk = kb16 >> 6, inner = kb16 & 63;
                    uint32_t off = sw128((uint32_t)(row * 128 + inner * 2));
                    char* dst = sm + OFF_B0 + chunk * B0_CS;
                    *(uint32_t*)(dst + off)     = pack_h2(v[j].x, v[j].y);
                    *(uint32_t*)(dst + off + 4) = pack_h2(v[j].z, v[j].w);
                }
            }
        }
    }

    // ---- W fragments from global: two m16 tiles (rows e0..+8, e0+16..+24) ----
    uint32_t A0[16][4], A1[16][4];
    {
        const int r0 = mq * 32 + (lane >> 2);
        const int c0 = (lane & 3) * 2;
#pragma unroll
        for (int kt = 0; kt < 16; kt++) {
            int k0 = kt * 16 + c0;
            float2 w00 = *(const float2*)(W_tree + r0 * 256 + k0);
            float2 w10 = *(const float2*)(W_tree + (r0 + 8) * 256 + k0);
            float2 w01 = *(const float2*)(W_tree + r0 * 256 + k0 + 8);
            float2 w11 = *(const float2*)(W_tree + (r0 + 8) * 256 + k0 + 8);
            A0[kt][0] = pack_h2(w00.x, w00.y);
            A0[kt][1] = pack_h2(w10.x, w10.y);
            A0[kt][2] = pack_h2(w01.x, w01.y);
            A0[kt][3] = pack_h2(w11.x, w11.y);
            float2 x00 = *(const float2*)(W_tree + (r0 + 16) * 256 + k0);
            float2 x10 = *(const float2*)(W_tree + (r0 + 24) * 256 + k0);
            float2 x01 = *(const float2*)(W_tree + (r0 + 16) * 256 + k0 + 8);
            float2 x11 = *(const float2*)(W_tree + (r0 + 24) * 256 + k0 + 8);
            A1[kt][0] = pack_h2(x00.x, x00.y);
            A1[kt][1] = pack_h2(x10.x, x10.y);
            A1[kt][2] = pack_h2(x01.x, x01.y);
            A1[kt][3] = pack_h2(x11.x, x11.y);
        }
    }
    float bias[4];
    bias[0] = b_tree[mq * 32 + (lane >> 2)];
    bias[1] = b_tree[mq * 32 + (lane >> 2) + 8];
    bias[2] = b_tree[mq * 32 + (lane >> 2) + 16];
    bias[3] = b_tree[mq * 32 + (lane >> 2) + 24];
    float* rootp = (float*)(sm + OFF_ROOT);
    __syncthreads();

    //        NT_TOT SPT LAST     src            dst
    run_level<32, 64, false>(sm, sb, OFF_B0, B0_CS, OFF_B1, B1_CS, A0, A1, bias, mq, g2, lane, rootp);
    __syncthreads();
    run_level<16, 32, false>(sm, sb, OFF_B1, B1_CS, OFF_B0, B0_CS, A0, A1, bias, mq, g2, lane, rootp);
    __syncthreads();
    run_level< 8, 16, false>(sm, sb, OFF_B0, B0_CS, OFF_B1, B1_CS, A0, A1, bias, mq, g2, lane, rootp);
    __syncthreads();
    run_level< 4,  8, false>(sm, sb, OFF_B1, B1_CS, OFF_B0, B0_CS, A0, A1, bias, mq, g2, lane, rootp);
    __syncthreads();
    run_level< 2,  4, false>(sm, sb, OFF_B0, B0_CS, OFF_B1, B1_CS, A0, A1, bias, mq, g2, lane, rootp);
    __syncthreads();
    run_level< 1,  2, false>(sm, sb, OFF_B1, B1_CS, OFF_B0, B0_CS, A0, A1, bias, mq, g2, lane, rootp);
    __syncthreads();
    run_level< 1,  1, true >(sm, sb, OFF_B0, B0_CS, OFF_B1, B1_CS, A0, A1, bias, mq, g2, lane, rootp);
    __syncthreads();

    // ---- classifier: 12 warp-dots (4 trees x 3 outputs) over 8 warps ----
    for (int idx = wq; idx < 12; idx += 8) {
        int tt = idx / 3, o = idx % 3;
        float p = 0.f;
#pragma unroll
        for (int k = 0; k < 4; k++) {
            int ee = lane + 32 * k;
            p += rootp[tt * 128 + ee] * W_cls[o * 128 + ee];
        }
#pragma unroll
        for (int off = 16; off; off >>= 1)
            p += __shfl_down_sync(0xffffffffu, p, off);
        if (lane == 0) out[(4 * b + tt) * NOUTC + o] = p + b_cls[o];
    }
}

extern "C" void kernel_launch(void* const* d_in, const int* in_sizes, int n_in,
                              void* d_out, int out_size)
{
    const void*  tokens = d_in[0];
    const float* emb    = (const float*)d_in[1];
    const float* W_tree = (const float*)d_in[2];
    const float* b_tree = (const float*)d_in[3];
    const float* W_cls  = (const float*)d_in[4];
    const float* b_cls  = (const float*)d_in[5];
    float* out = (float*)d_out;

    cudaFuncSetAttribute(tree_kernel,
                         cudaFuncAttributeMaxDynamicSharedMemorySize, SMEM_BYTES);

    detect_tok_kernel<<<1, 256>>>((const unsigned int*)tokens);
    tree_kernel<<<NB / 4, 256, SMEM_BYTES>>>(tokens, emb, W_tree, b_tree,
                                             W_cls, b_cls, out);
}

// round 15
// speedup vs baseline: 1.1718x; 1.1718x over previous
#include <cuda_runtime.h>
#include <cuda_fp16.h>
#include <stdint.h>

#define NB   4096
#define NOUTC 3

// ---- shared memory (bytes): ROOT(2x128 f32) | SCRATCH | B0: 128 rows | B1: 64 ----
#define OFF_ROOT    0
#define OFF_SCRATCH 1024
#define OFF_B0      2048
#define B0_CS       16384
#define OFF_B1      (OFF_B0 + 4 * B0_CS)     // 67584
#define B1_CS       8192
#define SMEM_BYTES  (OFF_B1 + 4 * B1_CS)     // 100352  (2 CTAs/SM)

__device__ int g_tok_is_i32;

__global__ void detect_tok_kernel(const unsigned int* __restrict__ w) {
    __shared__ int s;
    if (threadIdx.x == 0) s = 0;
    __syncthreads();
    int any = 0;
    for (int i = threadIdx.x; i < 2048; i += 256)
        any |= (w[2 * i + 1] != 0u);
    if (any) atomicOr(&s, 1);
    __syncthreads();
    if (threadIdx.x == 0) g_tok_is_i32 = s;
}

static __device__ __forceinline__ uint32_t sw128(uint32_t b) {
    return b ^ ((b >> 3) & 0x70);
}
static __device__ __forceinline__ uint32_t smem_u32(const void* p) {
    uint32_t a;
    asm("{ .reg .u64 t; cvta.to.shared.u64 t, %1; cvt.u32.u64 %0, t; }" : "=r"(a) : "l"(p));
    return a;
}
static __device__ __forceinline__ void ldsm4(uint32_t addr, uint32_t& r0, uint32_t& r1,
                                             uint32_t& r2, uint32_t& r3) {
    asm volatile("ldmatrix.sync.aligned.m8n8.x4.shared.b16 {%0,%1,%2,%3}, [%4];"
                 : "=r"(r0), "=r"(r1), "=r"(r2), "=r"(r3) : "r"(addr));
}
// transpose-store two 8x8 b16 matrices; lanes 0-7 address rows of matrix 0,
// lanes 8-15 rows of matrix 1.
static __device__ __forceinline__ void stsm2_trans(uint32_t addr, uint32_t f0, uint32_t f1) {
    asm volatile("stmatrix.sync.aligned.m8n8.x2.trans.shared.b16 [%0], {%1, %2};"
                 :: "r"(addr), "r"(f0), "r"(f1) : "memory");
}
static __device__ __forceinline__ void mma_f16(float& d0, float& d1, float& d2, float& d3,
                                               const uint32_t a[4], uint32_t b0, uint32_t b1) {
    asm volatile("mma.sync.aligned.m16n8k16.row.col.f32.f16.f16.f32 "
                 "{%0,%1,%2,%3}, {%4,%5,%6,%7}, {%8,%9}, {%0,%1,%2,%3};"
                 : "+f"(d0), "+f"(d1), "+f"(d2), "+f"(d3)
                 : "r"(a[0]), "r"(a[1]), "r"(a[2]), "r"(a[3]), "r"(b0), "r"(b1));
}
static __device__ __forceinline__ float tanh_fast(float x) {
    float t = __expf(2.0f * x);
    return 1.0f - __fdividef(2.0f, t + 1.0f);
}
static __device__ __forceinline__ uint32_t pack_h2(float x, float y) {
    __half h0 = __float2half_rn(x), h1 = __float2half_rn(y);
    return ((uint32_t)*(uint16_t*)&h1 << 16) | *(uint16_t*)&h0;
}

// One level over 2 trees; pipelined MMA -> prefetch -> STSM.trans epilogue.
template<int NTILES, int SPT, bool LAST>
static __device__ __forceinline__ void run_level(
    char* sm, uint32_t sb, uint32_t srcHi, uint32_t scs, uint32_t dstHi, uint32_t dcs,
    const uint32_t A[16][4],
    float bias0, float bias1, int wq, int lane, float* rootp)
{
    const int g = lane >> 3, lr = lane & 7;
    uint32_t Bh[16][2];

    // prologue: load tile 0
    {
        const int row = lr;
#pragma unroll
        for (int j = 0; j < 8; j++) {
            int kb = j * 64 + g * 16;
            uint32_t off = (uint32_t)((kb >> 7) * scs)
                         + sw128((uint32_t)(row * 128 + (kb & 127)));
            ldsm4(sb + srcHi + off,
                  Bh[2 * j][0], Bh[2 * j][1], Bh[2 * j + 1][0], Bh[2 * j + 1][1]);
        }
    }

#pragma unroll 1
    for (int nb = 0; nb < NTILES; nb++) {
        float c00 = 0.f, c01 = 0.f, c02 = 0.f, c03 = 0.f;
        float c10 = 0.f, c11 = 0.f, c12 = 0.f, c13 = 0.f;
#pragma unroll
        for (int kt = 0; kt < 16; kt += 2) {
            mma_f16(c00, c01, c02, c03, A[kt],     Bh[kt][0],     Bh[kt][1]);
            mma_f16(c10, c11, c12, c13, A[kt + 1], Bh[kt + 1][0], Bh[kt + 1][1]);
        }

        // prefetch next tile (WAR-safe in issue order)
        if (nb + 1 < NTILES) {
            const int row = (nb + 1) * 8 + lr;
#pragma unroll
            for (int j = 0; j < 8; j++) {
                int kb = j * 64 + g * 16;
                uint32_t off = (uint32_t)((kb >> 7) * scs)
                             + sw128((uint32_t)(row * 128 + (kb & 127)));
                ldsm4(sb + srcHi + off,
                      Bh[2 * j][0], Bh[2 * j][1], Bh[2 * j + 1][0], Bh[2 * j + 1][1]);
            }
        }

        float d0 = bias0 + (c00 + c10);
        float d1 = bias0 + (c01 + c11);
        float d2 = bias1 + (c02 + c12);
        float d3 = bias1 + (c03 + c13);

        if constexpr (!LAST) {
            // C-fragment == stmatrix source fragment; .trans writes [n][e] rows.
            uint32_t f0 = pack_h2(tanh_fast(d0), tanh_fast(d1));   // e-block wq*16
            uint32_t f1 = pack_h2(tanh_fast(d2), tanh_fast(d3));   // e-block wq*16+8
            const int j = lane & 7, m = (lane >> 3) & 1;
            const int nL2 = nb * 8 + j;
            uint32_t addr = sb + OFF_SCRATCH + (uint32_t)(lane * 16);
            if (lane < 16 && nL2 < 2 * SPT) {
                int tr = nL2 / SPT, ln = nL2 % SPT;      // SPT: power of 2
                int r = tr * (SPT / 2) + (ln >> 1);
                int k = ((ln & 1) << 7) + wq * 16 + m * 8;
                addr = sb + dstHi + (uint32_t)((k >> 6) * dcs)
                     + sw128((uint32_t)(r * 128 + (k & 63) * 2));
            }
            stsm2_trans(addr, f0, f1);
        } else {
            const int e0 = wq * 16 + (lane >> 2);
            if ((lane & 3) == 0) {
                rootp[e0]           = tanh_fast(d0);
                rootp[e0 + 8]       = tanh_fast(d2);
                rootp[128 + e0]     = tanh_fast(d1);
                rootp[128 + e0 + 8] = tanh_fast(d3);
            }
        }
    }
}

__global__ __launch_bounds__(256, 2)
void tree_kernel(const void* __restrict__ tokens_raw,
                 const float* __restrict__ emb,
                 const float* __restrict__ W_tree,
                 const float* __restrict__ b_tree,
                 const float* __restrict__ W_cls,
                 const float* __restrict__ b_cls,
                 float* __restrict__ out)
{
    extern __shared__ char sm[];
    const uint32_t sb = smem_u32(sm);
    const int tid = threadIdx.x, wq = tid >> 5, lane = tid & 31;
    const int b = blockIdx.x;                 // trees 2b, 2b+1

    // ---- leaf gather, MLP-8 batched: 1 token LDG/thread + shfl broadcast ----
    const int is32 = g_tok_is_i32;
    {
        const long long* t64 = (const long long*)tokens_raw;
        const int*       t32 = (const int*)tokens_raw;
        const int myLeaf = wq + 8 * lane;
        int myTok = is32 ? t32[b * 256 + myLeaf]
                         : (int)t64[b * 256 + myLeaf];
#pragma unroll
        for (int grp = 0; grp < 4; grp++) {
            float4 v[8];
#pragma unroll
            for (int j = 0; j < 8; j++) {
                int i = grp * 8 + j;
                int tk = __shfl_sync(0xffffffffu, myTok, i);
                v[j] = ((const float4*)emb)[(long long)tk * 32 + lane];
            }
#pragma unroll
            for (int j = 0; j < 8; j++) {
                int i = grp * 8 + j;
                int l = wq + 8 * i;
                int t = l >> 7, ll = l & 127;
                int row = t * 64 + (ll >> 1);
                int kb16 = ((ll & 1) << 7) + lane * 4;
                int chunk = kb16 >> 6, inner = kb16 & 63;
                uint32_t off = sw128((uint32_t)(row * 128 + inner * 2));
                char* dst = sm + OFF_B0 + chunk * B0_CS;
                *(uint32_t*)(dst + off)     = pack_h2(v[j].x, v[j].y);
                *(uint32_t*)(dst + off + 4) = pack_h2(v[j].z, v[j].w);
            }
        }
    }

    // ---- W fragments straight from global (m16n8k16 A-lane mapping), fp16 ----
    uint32_t A[16][4];
    {
        const int r0 = wq * 16 + (lane >> 2);
        const int c0 = (lane & 3) * 2;
#pragma unroll
        for (int kt = 0; kt < 16; kt++) {
            int k0 = kt * 16 + c0;
            float2 w00 = *(const float2*)(W_tree + r0 * 256 + k0);
            float2 w10 = *(const float2*)(W_tree + (r0 + 8) * 256 + k0);
            float2 w01 = *(const float2*)(W_tree + r0 * 256 + k0 + 8);
            float2 w11 = *(const float2*)(W_tree + (r0 + 8) * 256 + k0 + 8);
            A[kt][0] = pack_h2(w00.x, w00.y);
            A[kt][1] = pack_h2(w10.x, w10.y);
            A[kt][2] = pack_h2(w01.x, w01.y);
            A[kt][3] = pack_h2(w11.x, w11.y);
        }
    }
    const float bias0 = b_tree[wq * 16 + (lane >> 2)];
    const float bias1 = b_tree[wq * 16 + (lane >> 2) + 8];
    float* rootp = (float*)(sm + OFF_ROOT);
    __syncthreads();

    run_level<16, 64, false>(sm, sb, OFF_B0, B0_CS, OFF_B1, B1_CS, A, bias0, bias1, wq, lane, rootp);
    __syncthreads();
    run_level< 8, 32, false>(sm, sb, OFF_B1, B1_CS, OFF_B0, B0_CS, A, bias0, bias1, wq, lane, rootp);
    __syncthreads();
    run_level< 4, 16, false>(sm, sb, OFF_B0, B0_CS, OFF_B1, B1_CS, A, bias0, bias1, wq, lane, rootp);
    __syncthreads();
    run_level< 2,  8, false>(sm, sb, OFF_B1, B1_CS, OFF_B0, B0_CS, A, bias0, bias1, wq, lane, rootp);
    __syncthreads();
    run_level< 1,  4, false>(sm, sb, OFF_B0, B0_CS, OFF_B1, B1_CS, A, bias0, bias1, wq, lane, rootp);
    __syncthreads();
    run_level< 1,  2, false>(sm, sb, OFF_B1, B1_CS, OFF_B0, B0_CS, A, bias0, bias1, wq, lane, rootp);
    __syncthreads();
    run_level< 1,  1, true >(sm, sb, OFF_B0, B0_CS, OFF_B1, B1_CS, A, bias0, bias1, wq, lane, rootp);
    __syncthreads();

    // ---- classifier for both trees (6 warp-dots, fp32) ----
    if (tid < 192) {
        int w = tid >> 5;
        int t = (w >= 3) ? 1 : 0, o = w - t * 3;
        float p = 0.f;
#pragma unroll
        for (int k = 0; k < 4; k++) {
            int ee = lane + 32 * k;
            p += rootp[t * 128 + ee] * W_cls[o * 128 + ee];
        }
#pragma unroll
        for (int off = 16; off; off >>= 1)
            p += __shfl_down_sync(0xffffffffu, p, off);
        if (lane == 0) out[(2 * b + t) * NOUTC + o] = p + b_cls[o];
    }
}

extern "C" void kernel_launch(void* const* d_in, const int* in_sizes, int n_in,
                              void* d_out, int out_size)
{
    const void*  tokens = d_in[0];
    const float* emb    = (const float*)d_in[1];
    const float* W_tree = (const float*)d_in[2];
    const float* b_tree = (const float*)d_in[3];
    const float* W_cls  = (const float*)d_in[4];
    const float* b_cls  = (const float*)d_in[5];
    float* out = (float*)d_out;

    cudaFuncSetAttribute(tree_kernel,
                         cudaFuncAttributeMaxDynamicSharedMemorySize, SMEM_BYTES);

    detect_tok_kernel<<<1, 256>>>((const unsigned int*)tokens);
    tree_kernel<<<NB / 2, 256, SMEM_BYTES>>>(tokens, emb, W_tree, b_tree,
                                             W_cls, b_cls, out);
}

// round 17
// speedup vs baseline: 1.2746x; 1.0877x over previous
#include <cuda_runtime.h>
#include <cuda_fp16.h>
#include <stdint.h>

#define NB   4096
#define NOUTC 3

// ---- shared memory (bytes): ROOT(2x128 f32) | SCRATCH | B0: 128 rows | B1: 64 ----
#define OFF_ROOT    0
#define OFF_SCRATCH 1024
#define OFF_B0      2048
#define B0_CS       16384
#define OFF_B1      (OFF_B0 + 4 * B0_CS)     // 67584
#define B1_CS       8192
#define SMEM_BYTES  (OFF_B1 + 4 * B1_CS)     // 100352  (2 CTAs/SM)

__device__ int g_tok_is_i32;

__global__ void detect_tok_kernel(const unsigned int* __restrict__ w) {
    __shared__ int s;
    if (threadIdx.x == 0) s = 0;
    __syncthreads();
    int any = 0;
    for (int i = threadIdx.x; i < 2048; i += 256)
        any |= (w[2 * i + 1] != 0u);
    if (any) atomicOr(&s, 1);
    __syncthreads();
    if (threadIdx.x == 0) g_tok_is_i32 = s;
}

static __device__ __forceinline__ uint32_t sw128(uint32_t b) {
    return b ^ ((b >> 3) & 0x70);
}
static __device__ __forceinline__ uint32_t smem_u32(const void* p) {
    uint32_t a;
    asm("{ .reg .u64 t; cvta.to.shared.u64 t, %1; cvt.u32.u64 %0, t; }" : "=r"(a) : "l"(p));
    return a;
}
static __device__ __forceinline__ void ldsm4(uint32_t addr, uint32_t& r0, uint32_t& r1,
                                             uint32_t& r2, uint32_t& r3) {
    asm volatile("ldmatrix.sync.aligned.m8n8.x4.shared.b16 {%0,%1,%2,%3}, [%4];"
                 : "=r"(r0), "=r"(r1), "=r"(r2), "=r"(r3) : "r"(addr));
}
// transpose-store two 8x8 b16 matrices; lanes 0-15 supply row addresses.
static __device__ __forceinline__ void stsm2_trans(uint32_t addr, uint32_t f0, uint32_t f1) {
    asm volatile("stmatrix.sync.aligned.m8n8.x2.trans.shared.b16 [%0], {%1, %2};"
                 :: "r"(addr), "r"(f0), "r"(f1) : "memory");
}
static __device__ __forceinline__ void mma_f16(float& d0, float& d1, float& d2, float& d3,
                                               const uint32_t a[4], uint32_t b0, uint32_t b1) {
    asm volatile("mma.sync.aligned.m16n8k16.row.col.f32.f16.f16.f32 "
                 "{%0,%1,%2,%3}, {%4,%5,%6,%7}, {%8,%9}, {%0,%1,%2,%3};"
                 : "+f"(d0), "+f"(d1), "+f"(d2), "+f"(d3)
                 : "r"(a[0]), "r"(a[1]), "r"(a[2]), "r"(a[3]), "r"(b0), "r"(b1));
}
// single MUFU.TANH (sm_75+ base ISA), max err ~2^-11 — below fp16 storage rounding
static __device__ __forceinline__ float tanh_fast(float x) {
    float y;
    asm("tanh.approx.f32 %0, %1;" : "=f"(y) : "f"(x));
    return y;
}
static __device__ __forceinline__ uint32_t pack_h2(float x, float y) {
    __half h0 = __float2half_rn(x), h1 = __float2half_rn(y);
    return ((uint32_t)*(uint16_t*)&h1 << 16) | *(uint16_t*)&h0;
}

// One level over 2 trees; pipelined MMA -> prefetch -> STSM.trans epilogue.
template<int NTILES, int SPT, bool LAST>
static __device__ __forceinline__ void run_level(
    char* sm, uint32_t sb, uint32_t srcHi, uint32_t scs, uint32_t dstHi, uint32_t dcs,
    const uint32_t A[16][4],
    float bias0, float bias1, int wq, int lane, float* rootp)
{
    const int g = lane >> 3, lr = lane & 7;
    uint32_t Bh[16][2];

    // prologue: load tile 0
    {
        const int row = lr;
#pragma unroll
        for (int j = 0; j < 8; j++) {
            int kb = j * 64 + g * 16;
            uint32_t off = (uint32_t)((kb >> 7) * scs)
                         + sw128((uint32_t)(row * 128 + (kb & 127)));
            ldsm4(sb + srcHi + off,
                  Bh[2 * j][0], Bh[2 * j][1], Bh[2 * j + 1][0], Bh[2 * j + 1][1]);
        }
    }

#pragma unroll 1
    for (int nb = 0; nb < NTILES; nb++) {
        // bias folded into chain-0 init; chain-1 starts at 0
        float c00 = bias0, c01 = bias0, c02 = bias1, c03 = bias1;
        float c10 = 0.f,   c11 = 0.f,   c12 = 0.f,   c13 = 0.f;
#pragma unroll
        for (int kt = 0; kt < 16; kt += 2) {
            mma_f16(c00, c01, c02, c03, A[kt],     Bh[kt][0],     Bh[kt][1]);
            mma_f16(c10, c11, c12, c13, A[kt + 1], Bh[kt + 1][0], Bh[kt + 1][1]);
        }

        // prefetch next tile (WAR-safe in issue order)
        if (nb + 1 < NTILES) {
            const int row = (nb + 1) * 8 + lr;
#pragma unroll
            for (int j = 0; j < 8; j++) {
                int kb = j * 64 + g * 16;
                uint32_t off = (uint32_t)((kb >> 7) * scs)
                             + sw128((uint32_t)(row * 128 + (kb & 127)));
                ldsm4(sb + srcHi + off,
                      Bh[2 * j][0], Bh[2 * j][1], Bh[2 * j + 1][0], Bh[2 * j + 1][1]);
            }
        }

        float d0 = c00 + c10;
        float d1 = c01 + c11;
        float d2 = c02 + c12;
        float d3 = c03 + c13;

        if constexpr (!LAST) {
            // C-fragment == stmatrix source fragment; .trans writes [n][e] rows.
            uint32_t f0 = pack_h2(tanh_fast(d0), tanh_fast(d1));   // e-block wq*16
            uint32_t f1 = pack_h2(tanh_fast(d2), tanh_fast(d3));   // e-block wq*16+8
            const int j = lane & 7, m = (lane >> 3) & 1;
            const int nL2 = nb * 8 + j;
            uint32_t addr = sb + OFF_SCRATCH + (uint32_t)(lane * 16);
            if (lane < 16 && nL2 < 2 * SPT) {
                int tr = nL2 / SPT, ln = nL2 % SPT;      // SPT: power of 2
                int r = tr * (SPT / 2) + (ln >> 1);
                int k = ((ln & 1) << 7) + wq * 16 + m * 8;
                addr = sb + dstHi + (uint32_t)((k >> 6) * dcs)
                     + sw128((uint32_t)(r * 128 + (k & 63) * 2));
            }
            stsm2_trans(addr, f0, f1);
        } else {
            const int e0 = wq * 16 + (lane >> 2);
            if ((lane & 3) == 0) {
                rootp[e0]           = tanh_fast(d0);
                rootp[e0 + 8]       = tanh_fast(d2);
                rootp[128 + e0]     = tanh_fast(d1);
                rootp[128 + e0 + 8] = tanh_fast(d3);
            }
        }
    }
}

__global__ __launch_bounds__(256, 2)
void tree_kernel(const void* __restrict__ tokens_raw,
                 const float* __restrict__ emb,
                 const float* __restrict__ W_tree,
                 const float* __restrict__ b_tree,
                 const float* __restrict__ W_cls,
                 const float* __restrict__ b_cls,
                 float* __restrict__ out)
{
    extern __shared__ char sm[];
    const uint32_t sb = smem_u32(sm);
    const int tid = threadIdx.x, wq = tid >> 5, lane = tid & 31;
    const int b = blockIdx.x;                 // trees 2b, 2b+1

    // ---- leaf gather, MLP-8 batched: 1 token LDG/thread + shfl broadcast ----
    const int is32 = g_tok_is_i32;
    {
        const long long* t64 = (const long long*)tokens_raw;
        const int*       t32 = (const int*)tokens_raw;
        const int myLeaf = wq + 8 * lane;
        int myTok = is32 ? t32[b * 256 + myLeaf]
                         : (int)t64[b * 256 + myLeaf];
#pragma unroll
        for (int grp = 0; grp < 4; grp++) {
            float4 v[8];
#pragma unroll
            for (int j = 0; j < 8; j++) {
                int i = grp * 8 + j;
                int tk = __shfl_sync(0xffffffffu, myTok, i);
                v[j] = ((const float4*)emb)[(long long)tk * 32 + lane];
            }
#pragma unroll
            for (int j = 0; j < 8; j++) {
                int i = grp * 8 + j;
                int l = wq + 8 * i;
                int t = l >> 7, ll = l & 127;
                int row = t * 64 + (ll >> 1);
                int kb16 = ((ll & 1) << 7) + lane * 4;
                int chunk = kb16 >> 6, inner = kb16 & 63;
                uint32_t off = sw128((uint32_t)(row * 128 + inner * 2));
                char* dst = sm + OFF_B0 + chunk * B0_CS;
                *(uint32_t*)(dst + off)     = pack_h2(v[j].x, v[j].y);
                *(uint32_t*)(dst + off + 4) = pack_h2(v[j].z, v[j].w);
            }
        }
    }

    // ---- W fragments straight from global (m16n8k16 A-lane mapping), fp16 ----
    uint32_t A[16][4];
    {
        const int r0 = wq * 16 + (lane >> 2);
        const int c0 = (lane & 3) * 2;
#pragma unroll
        for (int kt = 0; kt < 16; kt++) {
            int k0 = kt * 16 + c0;
            float2 w00 = *(const float2*)(W_tree + r0 * 256 + k0);
            float2 w10 = *(const float2*)(W_tree + (r0 + 8) * 256 + k0);
            float2 w01 = *(const float2*)(W_tree + r0 * 256 + k0 + 8);
            float2 w11 = *(const float2*)(W_tree + (r0 + 8) * 256 + k0 + 8);
            A[kt][0] = pack_h2(w00.x, w00.y);
            A[kt][1] = pack_h2(w10.x, w10.y);
            A[kt][2] = pack_h2(w01.x, w01.y);
            A[kt][3] = pack_h2(w11.x, w11.y);
        }
    }
    const float bias0 = b_tree[wq * 16 + (lane >> 2)];
    const float bias1 = b_tree[wq * 16 + (lane >> 2) + 8];
    float* rootp = (float*)(sm + OFF_ROOT);
    __syncthreads();

    run_level<16, 64, false>(sm, sb, OFF_B0, B0_CS, OFF_B1, B1_CS, A, bias0, bias1, wq, lane, rootp);
    __syncthreads();
    run_level< 8, 32, false>(sm, sb, OFF_B1, B1_CS, OFF_B0, B0_CS, A, bias0, bias1, wq, lane, rootp);
    __syncthreads();
    run_level< 4, 16, false>(sm, sb, OFF_B0, B0_CS, OFF_B1, B1_CS, A, bias0, bias1, wq, lane, rootp);
    __syncthreads();
    run_level< 2,  8, false>(sm, sb, OFF_B1, B1_CS, OFF_B0, B0_CS, A, bias0, bias1, wq, lane, rootp);
    __syncthreads();
    run_level< 1,  4, false>(sm, sb, OFF_B0, B0_CS, OFF_B1, B1_CS, A, bias0, bias1, wq, lane, rootp);
    __syncthreads();
    run_level< 1,  2, false>(sm, sb, OFF_B1, B1_CS, OFF_B0, B0_CS, A, bias0, bias1, wq, lane, rootp);
    __syncthreads();
    run_level< 1,  1, true >(sm, sb, OFF_B0, B0_CS, OFF_B1, B1_CS, A, bias0, bias1, wq, lane, rootp);
    __syncthreads();

    // ---- classifier for both trees (6 warp-dots, fp32) ----
    if (tid < 192) {
        int w = tid >> 5;
        int t = (w >= 3) ? 1 : 0, o = w - t * 3;
        float p = 0.f;
#pragma unroll
        for (int k = 0; k < 4; k++) {
            int ee = lane + 32 * k;
            p += rootp[t * 128 + ee] * W_cls[o * 128 + ee];
        }
#pragma unroll
        for (int off = 16; off; off >>= 1)
            p += __shfl_down_sync(0xffffffffu, p, off);
        if (lane == 0) out[(2 * b + t) * NOUTC + o] = p + b_cls[o];
    }
}

extern "C" void kernel_launch(void* const* d_in, const int* in_sizes, int n_in,
                              void* d_out, int out_size)
{
    const void*  tokens = d_in[0];
    const float* emb    = (const float*)d_in[1];
    const float* W_tree = (const float*)d_in[2];
    const float* b_tree = (const float*)d_in[3];
    const float* W_cls  = (const float*)d_in[4];
    const float* b_cls  = (const float*)d_in[5];
    float* out = (float*)d_out;

    cudaFuncSetAttribute(tree_kernel,
                         cudaFuncAttributeMaxDynamicSharedMemorySize, SMEM_BYTES);

    detect_tok_kernel<<<1, 256>>>((const unsigned int*)tokens);
    tree_kernel<<<NB / 2, 256, SMEM_BYTES>>>(tokens, emb, W_tree, b_tree,
                                             W_cls, b_cls, out);
}